// round 10
// baseline (speedup 1.0000x reference)
#include <cuda_runtime.h>
#include <cuda_bf16.h>
#include <cuda_fp8.h>
#include <cstdint>

// ============================================================================
// out[8192,4096] = fp8_q(x) @ fp8_q(w)^T + bias ; amax EMA scalars at tail.
// sm_103 base ISA. bf16 mma.sync GEMM.
// R10: warp-specialized producer (1 warp, cp.async + mbarrier) + 4 consumer
//      warps (64x64), no __syncthreads in mainloop. 2 CTA/SM.
// ============================================================================

#define FP8_MAX   448.0f
#define AMAX_EPS  1e-8f
#define MOMENTUM  0.95f

static constexpr int M_DIM = 8192;
static constexpr int N_DIM = 4096;
static constexpr int K_DIM = 4096;

static constexpr int BM = 128;
static constexpr int BN = 128;
static constexpr int BK = 64;                    // bf16 elems -> 128B rows
static constexpr int STAGES = 3;
static constexpr int KITERS = K_DIM / BK;        // 64

static constexpr int STAGE_A = BM * BK * 2;      // 16384 B
static constexpr int STAGE_B = BN * BK * 2;      // 16384 B
static constexpr int SOFF_BIAS  = 64;            // 512 B of bias
static constexpr int SOFF_TILES = 1024;
static constexpr int SMEM_BYTES = SOFF_TILES + STAGES * (STAGE_A + STAGE_B); // 99328

// mbarriers in smem: full[s] at s*8, free[s] at 24 + s*8
__device__ __forceinline__ uint32_t mb_full(uint32_t sb, int s) { return sb + s * 8; }
__device__ __forceinline__ uint32_t mb_free(uint32_t sb, int s) { return sb + 24 + s * 8; }

// Scratch: scaled-quantized values stored as bf16 (exact superset of e4m3)
__device__ __nv_bfloat16 g_xb[(size_t)M_DIM * K_DIM];   // 64 MB
__device__ __nv_bfloat16 g_wb[(size_t)N_DIM * K_DIM];   // 32 MB
__device__ float g_amax[2];

// ============================================================================
// helpers
// ============================================================================
__device__ __forceinline__ uint32_t smem_u32(const void* p) {
    uint32_t a;
    asm("{ .reg .u64 t; cvta.to.shared.u64 t, %1; cvt.u32.u64 %0, t; }"
        : "=r"(a) : "l"(p));
    return a;
}

__device__ __forceinline__ void cp16(uint32_t dst, const void* src) {
    asm volatile("cp.async.cg.shared.global [%0], [%1], 16;"
                 :: "r"(dst), "l"(src) : "memory");
}

__device__ __forceinline__ void mbar_init(uint32_t addr, uint32_t cnt) {
    asm volatile("mbarrier.init.shared.b64 [%0], %1;" :: "r"(addr), "r"(cnt) : "memory");
}

__device__ __forceinline__ void mbar_arrive(uint32_t addr) {
    asm volatile("mbarrier.arrive.shared.b64 _, [%0];" :: "r"(addr) : "memory");
}

__device__ __forceinline__ void cpasync_mbar_arrive(uint32_t addr) {
    asm volatile("cp.async.mbarrier.arrive.noinc.shared.b64 [%0];"
                 :: "r"(addr) : "memory");
}

__device__ __forceinline__ void mbar_wait(uint32_t addr, uint32_t parity) {
    asm volatile(
        "{\n\t.reg .pred P;\n"
        "WAIT_%=:\n\t"
        "mbarrier.try_wait.parity.acquire.cta.shared::cta.b64 P, [%0], %1;\n\t"
        "@P bra DONE_%=;\n\t"
        "bra WAIT_%=;\n"
        "DONE_%=:\n\t}"
        :: "r"(addr), "r"(parity) : "memory");
}

__device__ __forceinline__ void ldmatrix_x4(uint32_t* r, uint32_t addr) {
    asm volatile("ldmatrix.sync.aligned.m8n8.x4.shared.b16 {%0,%1,%2,%3}, [%4];"
                 : "=r"(r[0]), "=r"(r[1]), "=r"(r[2]), "=r"(r[3]) : "r"(addr));
}

__device__ __forceinline__ void mma_bf16(float* c, const uint32_t* a, const uint32_t* b) {
    asm volatile(
        "mma.sync.aligned.m16n8k16.row.col.f32.bf16.bf16.f32 "
        "{%0,%1,%2,%3}, {%4,%5,%6,%7}, {%8,%9}, {%0,%1,%2,%3};"
        : "+f"(c[0]), "+f"(c[1]), "+f"(c[2]), "+f"(c[3])
        : "r"(a[0]), "r"(a[1]), "r"(a[2]), "r"(a[3]), "r"(b[0]), "r"(b[1]));
}

// ============================================================================
// small kernels
// ============================================================================
__global__ void init_kernel() { g_amax[0] = 0.0f; g_amax[1] = 0.0f; }

// fp32 -> e4m3(RN,satfinite) -> bf16 (exact), scaled; block-reduced abs-max.
__global__ void __launch_bounds__(256) quant_kernel(
    const float* __restrict__ src, const float* __restrict__ amax_buf,
    int which, int n16)
{
    __nv_bfloat16* dst = which ? g_wb : g_xb;
    float* gm = &g_amax[which];

    const int i = blockIdx.x * blockDim.x + threadIdx.x;
    const float scale = FP8_MAX / fmaxf(*amax_buf, AMAX_EPS);

    float m = 0.0f;
    if (i < n16) {
        const float4* s4 = reinterpret_cast<const float4*>(src) + (size_t)i * 4;
        uint32_t outw[8];
        #pragma unroll
        for (int j = 0; j < 4; j++) {
            float4 v = s4[j];
            m = fmaxf(m, fmaxf(fmaxf(fabsf(v.x), fabsf(v.y)),
                               fmaxf(fabsf(v.z), fabsf(v.w))));
            float f[4];
            f[0] = v.x * scale; f[1] = v.y * scale;
            f[2] = v.z * scale; f[3] = v.w * scale;
            unsigned short us[4];
            #pragma unroll
            for (int e = 0; e < 4; e++) {
                __nv_fp8_e4m3 q;
                q.__x = __nv_cvt_float_to_fp8(f[e], __NV_SATFINITE, __NV_E4M3);
                us[e] = __bfloat16_as_ushort(__float2bfloat16(float(q)));
            }
            outw[j * 2 + 0] = (uint32_t)us[0] | ((uint32_t)us[1] << 16);
            outw[j * 2 + 1] = (uint32_t)us[2] | ((uint32_t)us[3] << 16);
        }
        uint4* d4 = reinterpret_cast<uint4*>(dst) + (size_t)i * 2;
        d4[0] = make_uint4(outw[0], outw[1], outw[2], outw[3]);
        d4[1] = make_uint4(outw[4], outw[5], outw[6], outw[7]);
    }

    #pragma unroll
    for (int off = 16; off; off >>= 1)
        m = fmaxf(m, __shfl_xor_sync(0xFFFFFFFFu, m, off));
    __shared__ float wmax[8];
    const int wid = threadIdx.x >> 5, lid = threadIdx.x & 31;
    if (lid == 0) wmax[wid] = m;
    __syncthreads();
    if (wid == 0) {
        float mm = (lid < 8) ? wmax[lid] : 0.0f;
        #pragma unroll
        for (int off = 4; off; off >>= 1)
            mm = fmaxf(mm, __shfl_xor_sync(0xFFFFFFFFu, mm, off));
        if (lid == 0)
            atomicMax(reinterpret_cast<int*>(gm), __float_as_int(mm));
    }
}

__global__ void finalize_kernel(const float* __restrict__ ia,
                                const float* __restrict__ wa,
                                float* __restrict__ out_tail)
{
    out_tail[0] = fmaxf(fmaxf(*ia * MOMENTUM, g_amax[0]), AMAX_EPS);
    out_tail[1] = fmaxf(fmaxf(*wa * MOMENTUM, g_amax[1]), AMAX_EPS);
}

// ============================================================================
// GEMM: CTA 128x128x64, 4 consumer warps (2x2, 64x64 tiles) + 1 producer warp
// ============================================================================
__global__ void __launch_bounds__(160, 2)
gemm_kernel(const float* __restrict__ bias,
            const float* __restrict__ ia, const float* __restrict__ wa,
            float* __restrict__ out)
{
    extern __shared__ char smem[];
    const uint32_t sbase = smem_u32(smem);

    // L2-friendly rasterization: group 16 m-tiles
    constexpr int NT = N_DIM / BN;   // 32
    constexpr int G = 16;
    const int linear = blockIdx.x;
    const int group = linear / (G * NT);
    const int rem   = linear % (G * NT);
    const int mtile = group * G + (rem % G);
    const int ntile = rem / G;

    const int tid = threadIdx.x;
    const int wid = tid >> 5, lane = tid & 31;

    float* bs = reinterpret_cast<float*>(smem + SOFF_BIAS);
    if (tid < BN) bs[tid] = bias[ntile * BN + tid];

    if (tid == 0) {
        #pragma unroll
        for (int s = 0; s < STAGES; s++) {
            mbar_init(mb_full(sbase, s), 32);    // producer cp.async arrivals
            mbar_init(mb_free(sbase, s), 128);   // consumer arrivals
        }
    }
    __syncthreads();   // barriers + bias visible; only sync in the kernel

    const __nv_bfloat16* Ag = g_xb + (size_t)mtile * BM * K_DIM;
    const __nv_bfloat16* Bg = g_wb + (size_t)ntile * BN * K_DIM;

    if (wid == 4) {
        // ---------------- producer warp ----------------
        // Each lane: c16 = lane&7 (16B column), rows r0+4j, j=0..31 (64 rows?
        // no: 128 rows / 32 lanes -> each lane covers rows lane>>3 + 4j).
        const int c16 = lane & 7;
        const int r0 = lane >> 3;                         // 0..3
        const uint32_t col0 = (uint32_t)(c16 * 16) ^ ((r0 & 7) << 4);
        const uint32_t col1 = (uint32_t)(c16 * 16) ^ (((r0 + 4) & 7) << 4);
        const __nv_bfloat16* gA = Ag + (size_t)r0 * K_DIM + c16 * 8;
        const __nv_bfloat16* gB = Bg + (size_t)r0 * K_DIM + c16 * 8;

        int b = 0;                   // write-stage cursor
        int fb = 0, fpar = 0;        // free-wait cursor (starts at k==STAGES)
        for (int k = 0; k < KITERS; k++) {
            if (k >= STAGES) {
                mbar_wait(mb_free(sbase, fb), fpar);
                if (++fb == STAGES) { fb = 0; fpar ^= 1; }
            }
            const uint32_t sA = sbase + SOFF_TILES + b * STAGE_A;
            const uint32_t sB = sbase + SOFF_TILES + STAGES * STAGE_A + b * STAGE_B;
            const int k0 = k * BK;
            const uint32_t dA = sA + r0 * 128;
            const uint32_t dB = sB + r0 * 128;
            #pragma unroll
            for (int j = 0; j < 32; j += 2) {
                cp16(dA + (4 * j) * 128 + col0, gA + (size_t)(4 * j) * K_DIM + k0);
                cp16(dA + (4 * j + 4) * 128 + col1, gA + (size_t)(4 * j + 4) * K_DIM + k0);
            }
            #pragma unroll
            for (int j = 0; j < 32; j += 2) {
                cp16(dB + (4 * j) * 128 + col0, gB + (size_t)(4 * j) * K_DIM + k0);
                cp16(dB + (4 * j + 4) * 128 + col1, gB + (size_t)(4 * j + 4) * K_DIM + k0);
            }
            cpasync_mbar_arrive(mb_full(sbase, b));
            if (++b == STAGES) b = 0;
        }
        return;   // producer exits; no further block-wide syncs exist
    }

    // ---------------- consumer warps (wid 0..3) ----------------
    const int warp_m = wid >> 1;          // 0..1 (64 rows)
    const int warp_n = wid & 1;           // 0..1 (64 cols)

    // ldmatrix lane->address mapping
    // A x4: r0=(m0-7,klo) r1=(m8-15,klo) r2=(m0-7,khi) r3=(m8-15,khi)
    const int a_row_l = warp_m * 64 + (lane & 15);
    const uint32_t a_khalf = (lane >> 4) << 4;      // 0 or 16 bytes
    // B x4: r0,r1 = n0-7 pair ; r2,r3 = n8-15 pair
    const int b_row_l = warp_n * 64 + (lane & 7) + ((lane >> 4) << 3);
    const uint32_t b_khalf = ((lane >> 3) & 1) << 4;

    float acc[4][8][4];
    #pragma unroll
    for (int i = 0; i < 4; i++)
        #pragma unroll
        for (int j = 0; j < 8; j++)
            #pragma unroll
            for (int e = 0; e < 4; e++) acc[i][j][e] = 0.0f;

    uint32_t afrag[4][4];       // single-buffered (reloaded per ks)
    uint32_t bfrag[2][4][4];    // double-buffered

    int b = 0, par = 0;
    for (int k = 0; k < KITERS; k++) {
        mbar_wait(mb_full(sbase, b), par);
        const uint32_t sA = sbase + SOFF_TILES + b * STAGE_A;
        const uint32_t sB = sbase + SOFF_TILES + STAGES * STAGE_A + b * STAGE_B;

        // preload B ks0
        #pragma unroll
        for (int nh = 0; nh < 4; nh++) {
            int row = b_row_l + nh * 16;
            uint32_t col = b_khalf;
            ldmatrix_x4(bfrag[0][nh], sB + row * 128 + (col ^ ((row & 7) << 4)));
        }
        #pragma unroll
        for (int ks = 0; ks < BK / 16; ks++) {
            const int cur = ks & 1;
            // load A for this ks (single-buffered)
            #pragma unroll
            for (int mi = 0; mi < 4; mi++) {
                int row = a_row_l + mi * 16;
                uint32_t col = (uint32_t)ks * 32 + a_khalf;
                ldmatrix_x4(afrag[mi], sA + row * 128 + (col ^ ((row & 7) << 4)));
            }
            // prefetch B for next ks
            if (ks + 1 < BK / 16) {
                #pragma unroll
                for (int nh = 0; nh < 4; nh++) {
                    int row = b_row_l + nh * 16;
                    uint32_t col = (uint32_t)(ks + 1) * 32 + b_khalf;
                    ldmatrix_x4(bfrag[cur ^ 1][nh],
                                sB + row * 128 + (col ^ ((row & 7) << 4)));
                }
            }
            #pragma unroll
            for (int mi = 0; mi < 4; mi++)
                #pragma unroll
                for (int ni = 0; ni < 8; ni++)
                    mma_bf16(acc[mi][ni], afrag[mi],
                             bfrag[cur][ni >> 1] + (ni & 1) * 2);
        }
        mbar_arrive(mb_free(sbase, b));
        if (++b == STAGES) { b = 0; par ^= 1; }
    }

    // epilogue: descale + bias (consumers only)
    const float inv = (fmaxf(*ia, AMAX_EPS) * (1.0f / FP8_MAX)) *
                      (fmaxf(*wa, AMAX_EPS) * (1.0f / FP8_MAX));
    const int g = lane >> 2, t = lane & 3;
    #pragma unroll
    for (int mi = 0; mi < 4; mi++) {
        #pragma unroll
        for (int ni = 0; ni < 8; ni++) {
            const int col_l = warp_n * 64 + ni * 8 + t * 2;
            const int col = ntile * BN + col_l;
            const float b0 = bs[col_l], b1 = bs[col_l + 1];
            const int r0 = mtile * BM + warp_m * 64 + mi * 16 + g;
            float2 v0, v1;
            v0.x = acc[mi][ni][0] * inv + b0;
            v0.y = acc[mi][ni][1] * inv + b1;
            v1.x = acc[mi][ni][2] * inv + b0;
            v1.y = acc[mi][ni][3] * inv + b1;
            *reinterpret_cast<float2*>(out + (size_t)r0 * N_DIM + col) = v0;
            *reinterpret_cast<float2*>(out + (size_t)(r0 + 8) * N_DIM + col) = v1;
        }
    }
}

// ============================================================================
// launch
// ============================================================================
extern "C" void kernel_launch(void* const* d_in, const int* in_sizes, int n_in,
                              void* d_out, int out_size)
{
    const float* x    = (const float*)d_in[0];
    const float* w    = (const float*)d_in[1];
    const float* bias = (const float*)d_in[2];
    const float* ia   = (const float*)d_in[3];
    const float* wa   = (const float*)d_in[4];
    float* out = (float*)d_out;

    cudaFuncSetAttribute(gemm_kernel,
                         cudaFuncAttributeMaxDynamicSharedMemorySize, SMEM_BYTES);

    init_kernel<<<1, 1>>>();

    const int n16_x = (M_DIM * K_DIM) / 16;
    const int n16_w = (N_DIM * K_DIM) / 16;
    quant_kernel<<<n16_x / 256, 256>>>(x, ia, 0, n16_x);
    quant_kernel<<<n16_w / 256, 256>>>(w, wa, 1, n16_w);

    const int ntiles = (M_DIM / BM) * (N_DIM / BN);   // 2048
    gemm_kernel<<<ntiles, 160, SMEM_BYTES>>>(bias, ia, wa, out);

    finalize_kernel<<<1, 1>>>(ia, wa, out + (size_t)M_DIM * N_DIM);
}

// round 12
// speedup vs baseline: 1.1048x; 1.1048x over previous
#include <cuda_runtime.h>
#include <cuda_bf16.h>
#include <cuda_fp8.h>
#include <cstdint>

// ============================================================================
// out[8192,4096] = fp8_q(x) @ fp8_q(w)^T + bias ; amax EMA scalars at tail.
// sm_103 base ISA: bf16 mma.sync.
// R11: R9 config (CTA 128x128, 4 warps 64x64, 3 stages, 2 CTA/SM) +
//      per-CTA K-phase stagger to decorrelate co-resident CTAs' barriers.
// ============================================================================

#define FP8_MAX   448.0f
#define AMAX_EPS  1e-8f
#define MOMENTUM  0.95f

static constexpr int M_DIM = 8192;
static constexpr int N_DIM = 4096;
static constexpr int K_DIM = 4096;

static constexpr int BM = 128;
static constexpr int BN = 128;
static constexpr int BK = 64;                    // bf16 elems -> 128B rows
static constexpr int STAGES = 3;
static constexpr int KITERS = K_DIM / BK;        // 64

static constexpr int STAGE_A = BM * BK * 2;      // 16384 B
static constexpr int STAGE_B = BN * BK * 2;      // 16384 B
static constexpr int SMEM_BYTES = STAGES * (STAGE_A + STAGE_B);  // 98304

// Scratch: scaled-quantized values stored as bf16 (exact superset of e4m3)
__device__ __nv_bfloat16 g_xb[(size_t)M_DIM * K_DIM];   // 64 MB
__device__ __nv_bfloat16 g_wb[(size_t)N_DIM * K_DIM];   // 32 MB
__device__ float g_amax[2];

// ============================================================================
// helpers
// ============================================================================
__device__ __forceinline__ uint32_t smem_u32(const void* p) {
    uint32_t a;
    asm("{ .reg .u64 t; cvta.to.shared.u64 t, %1; cvt.u32.u64 %0, t; }"
        : "=r"(a) : "l"(p));
    return a;
}

__device__ __forceinline__ void cp16(uint32_t dst, const void* src) {
    asm volatile("cp.async.cg.shared.global [%0], [%1], 16;"
                 :: "r"(dst), "l"(src) : "memory");
}

__device__ __forceinline__ void ldmatrix_x4(uint32_t* r, uint32_t addr) {
    asm volatile("ldmatrix.sync.aligned.m8n8.x4.shared.b16 {%0,%1,%2,%3}, [%4];"
                 : "=r"(r[0]), "=r"(r[1]), "=r"(r[2]), "=r"(r[3]) : "r"(addr));
}

__device__ __forceinline__ void mma_bf16(float* c, const uint32_t* a, const uint32_t* b) {
    asm volatile(
        "mma.sync.aligned.m16n8k16.row.col.f32.bf16.bf16.f32 "
        "{%0,%1,%2,%3}, {%4,%5,%6,%7}, {%8,%9}, {%0,%1,%2,%3};"
        : "+f"(c[0]), "+f"(c[1]), "+f"(c[2]), "+f"(c[3])
        : "r"(a[0]), "r"(a[1]), "r"(a[2]), "r"(a[3]), "r"(b[0]), "r"(b[1]));
}

// ============================================================================
// small kernels
// ============================================================================
__global__ void init_kernel() { g_amax[0] = 0.0f; g_amax[1] = 0.0f; }

// fp32 -> e4m3(RN,satfinite) -> bf16 (exact), scaled; block-reduced abs-max.
__global__ void __launch_bounds__(256) quant_kernel(
    const float* __restrict__ src, const float* __restrict__ amax_buf,
    int which, int n16)
{
    __nv_bfloat16* dst = which ? g_wb : g_xb;
    float* gm = &g_amax[which];

    const int i = blockIdx.x * blockDim.x + threadIdx.x;
    const float scale = FP8_MAX / fmaxf(*amax_buf, AMAX_EPS);

    float m = 0.0f;
    if (i < n16) {
        const float4* s4 = reinterpret_cast<const float4*>(src) + (size_t)i * 4;
        uint32_t outw[8];
        #pragma unroll
        for (int j = 0; j < 4; j++) {
            float4 v = s4[j];
            m = fmaxf(m, fmaxf(fmaxf(fabsf(v.x), fabsf(v.y)),
                               fmaxf(fabsf(v.z), fabsf(v.w))));
            float f[4];
            f[0] = v.x * scale; f[1] = v.y * scale;
            f[2] = v.z * scale; f[3] = v.w * scale;
            unsigned short us[4];
            #pragma unroll
            for (int e = 0; e < 4; e++) {
                __nv_fp8_e4m3 q;
                q.__x = __nv_cvt_float_to_fp8(f[e], __NV_SATFINITE, __NV_E4M3);
                us[e] = __bfloat16_as_ushort(__float2bfloat16(float(q)));
            }
            outw[j * 2 + 0] = (uint32_t)us[0] | ((uint32_t)us[1] << 16);
            outw[j * 2 + 1] = (uint32_t)us[2] | ((uint32_t)us[3] << 16);
        }
        uint4* d4 = reinterpret_cast<uint4*>(dst) + (size_t)i * 2;
        d4[0] = make_uint4(outw[0], outw[1], outw[2], outw[3]);
        d4[1] = make_uint4(outw[4], outw[5], outw[6], outw[7]);
    }

    #pragma unroll
    for (int off = 16; off; off >>= 1)
        m = fmaxf(m, __shfl_xor_sync(0xFFFFFFFFu, m, off));
    __shared__ float wmax[8];
    const int wid = threadIdx.x >> 5, lid = threadIdx.x & 31;
    if (lid == 0) wmax[wid] = m;
    __syncthreads();
    if (wid == 0) {
        float mm = (lid < 8) ? wmax[lid] : 0.0f;
        #pragma unroll
        for (int off = 4; off; off >>= 1)
            mm = fmaxf(mm, __shfl_xor_sync(0xFFFFFFFFu, mm, off));
        if (lid == 0)
            atomicMax(reinterpret_cast<int*>(gm), __float_as_int(mm));
    }
}

__global__ void finalize_kernel(const float* __restrict__ ia,
                                const float* __restrict__ wa,
                                float* __restrict__ out_tail)
{
    out_tail[0] = fmaxf(fmaxf(*ia * MOMENTUM, g_amax[0]), AMAX_EPS);
    out_tail[1] = fmaxf(fmaxf(*wa * MOMENTUM, g_amax[1]), AMAX_EPS);
}

// ============================================================================
// GEMM: CTA 128x128x64, 4 warps (2x2), warp tile 64x64, mma.sync bf16
// ============================================================================
__global__ void __launch_bounds__(128, 2)
gemm_kernel(const float* __restrict__ bias,
            const float* __restrict__ ia, const float* __restrict__ wa,
            float* __restrict__ out)
{
    extern __shared__ char smem[];
    const uint32_t sbase = smem_u32(smem);

    // L2-friendly rasterization: group 16 m-tiles
    constexpr int NT = N_DIM / BN;   // 32
    constexpr int G = 16;
    const int linear = blockIdx.x;
    const int group = linear / (G * NT);
    const int rem   = linear % (G * NT);
    const int mtile = group * G + (rem % G);
    const int ntile = rem / G;

    // K-phase stagger: odd CTAs sweep K starting at the midpoint (rotating).
    // Decorrelates co-resident CTAs' barrier/memory phases; fp32 accumulation
    // order changes but stays well within tolerance.
    const int phase = (linear & 1) ? (KITERS / 2) : 0;

    const int tid = threadIdx.x;
    const int wid = tid >> 5, lane = tid & 31;
    const int warp_m = wid >> 1;          // 0..1 (64 rows each)
    const int warp_n = wid & 1;           // 0..1 (64 cols each)

    __shared__ float bs[BN];
    if (tid < BN) bs[tid] = bias[ntile * BN + tid];

    const __nv_bfloat16* Ag = g_xb + (size_t)mtile * BM * K_DIM;
    const __nv_bfloat16* Bg = g_wb + (size_t)ntile * BN * K_DIM;

    // 1024 16B chunks per tile, 8 per thread (128 threads)
    auto issue_stage = [&](int kiter, int stage) {
        const int kk = (kiter + phase < KITERS) ? (kiter + phase)
                                                : (kiter + phase - KITERS);
        const int k0 = kk * BK;
        const uint32_t sA = sbase + stage * STAGE_A;
        const uint32_t sB = sbase + STAGES * STAGE_A + stage * STAGE_B;
        #pragma unroll
        for (int j = 0; j < 8; j++) {
            int idx = tid + j * 128;
            int row = idx >> 3, c16 = idx & 7;
            uint32_t swcol = (c16 * 16) ^ ((row & 7) << 4);
            cp16(sA + row * 128 + swcol, Ag + (size_t)row * K_DIM + k0 + c16 * 8);
        }
        #pragma unroll
        for (int j = 0; j < 8; j++) {
            int idx = tid + j * 128;
            int row = idx >> 3, c16 = idx & 7;
            uint32_t swcol = (c16 * 16) ^ ((row & 7) << 4);
            cp16(sB + row * 128 + swcol, Bg + (size_t)row * K_DIM + k0 + c16 * 8);
        }
        asm volatile("cp.async.commit_group;" ::: "memory");
    };

    float acc[4][8][4];
    #pragma unroll
    for (int i = 0; i < 4; i++)
        #pragma unroll
        for (int j = 0; j < 8; j++)
            #pragma unroll
            for (int e = 0; e < 4; e++) acc[i][j][e] = 0.0f;

    // prologue: 2 stages in flight
    issue_stage(0, 0);
    issue_stage(1, 1);

    // ldmatrix lane->address mapping
    // A x4: r0=(m0-7,klo) r1=(m8-15,klo) r2=(m0-7,khi) r3=(m8-15,khi)
    const int a_row_l = warp_m * 64 + (lane & 15);
    const uint32_t a_khalf = (lane >> 4) << 4;      // 0 or 16 bytes
    // B x4: r0,r1 = n0-7 pair ; r2,r3 = n8-15 pair
    const int b_row_l = warp_n * 64 + (lane & 7) + ((lane >> 4) << 3);
    const uint32_t b_khalf = ((lane >> 3) & 1) << 4;

    // double-buffered fragments: A 64 rows (4 x4), B 64 cols (4 x4)
    uint32_t afrag[2][4][4], bfrag[2][4][4];

    auto load_frags = [&](int buf, uint32_t sA, uint32_t sB, int ks) {
        #pragma unroll
        for (int mi = 0; mi < 4; mi++) {
            int row = a_row_l + mi * 16;
            uint32_t col = (uint32_t)ks * 32 + a_khalf;
            ldmatrix_x4(afrag[buf][mi], sA + row * 128 + (col ^ ((row & 7) << 4)));
        }
        #pragma unroll
        for (int nh = 0; nh < 4; nh++) {
            int row = b_row_l + nh * 16;
            uint32_t col = (uint32_t)ks * 32 + b_khalf;
            ldmatrix_x4(bfrag[buf][nh], sB + row * 128 + (col ^ ((row & 7) << 4)));
        }
    };

    for (int k = 0; k < KITERS; k++) {
        asm volatile("cp.async.wait_group 1;" ::: "memory");
        __syncthreads();
        // Stage (k+2)%3 was last READ at iter k-1; the sync above guarantees
        // every warp finished those reads -> safe to overwrite.
        if (k + 2 < KITERS) issue_stage(k + 2, (k + 2) % STAGES);
        else asm volatile("cp.async.commit_group;" ::: "memory");

        const int stage = k % STAGES;
        const uint32_t sA = sbase + stage * STAGE_A;
        const uint32_t sB = sbase + STAGES * STAGE_A + stage * STAGE_B;

        load_frags(0, sA, sB, 0);
        #pragma unroll
        for (int ks = 0; ks < BK / 16; ks++) {
            const int cur = ks & 1;
            if (ks + 1 < BK / 16) load_frags(cur ^ 1, sA, sB, ks + 1);
            #pragma unroll
            for (int mi = 0; mi < 4; mi++)
                #pragma unroll
                for (int ni = 0; ni < 8; ni++)
                    mma_bf16(acc[mi][ni], afrag[cur][mi],
                             bfrag[cur][ni >> 1] + (ni & 1) * 2);
        }
    }

    // epilogue: descale + bias
    const float inv = (fmaxf(*ia, AMAX_EPS) * (1.0f / FP8_MAX)) *
                      (fmaxf(*wa, AMAX_EPS) * (1.0f / FP8_MAX));
    const int g = lane >> 2, t = lane & 3;
    #pragma unroll
    for (int mi = 0; mi < 4; mi++) {
        #pragma unroll
        for (int ni = 0; ni < 8; ni++) {
            const int col_l = warp_n * 64 + ni * 8 + t * 2;
            const int col = ntile * BN + col_l;
            const float b0 = bs[col_l], b1 = bs[col_l + 1];
            const int r0 = mtile * BM + warp_m * 64 + mi * 16 + g;
            float2 v0, v1;
            v0.x = acc[mi][ni][0] * inv + b0;
            v0.y = acc[mi][ni][1] * inv + b1;
            v1.x = acc[mi][ni][2] * inv + b0;
            v1.y = acc[mi][ni][3] * inv + b1;
            *reinterpret_cast<float2*>(out + (size_t)r0 * N_DIM + col) = v0;
            *reinterpret_cast<float2*>(out + (size_t)(r0 + 8) * N_DIM + col) = v1;
        }
    }
}

// ============================================================================
// launch
// ============================================================================
extern "C" void kernel_launch(void* const* d_in, const int* in_sizes, int n_in,
                              void* d_out, int out_size)
{
    const float* x    = (const float*)d_in[0];
    const float* w    = (const float*)d_in[1];
    const float* bias = (const float*)d_in[2];
    const float* ia   = (const float*)d_in[3];
    const float* wa   = (const float*)d_in[4];
    float* out = (float*)d_out;

    cudaFuncSetAttribute(gemm_kernel,
                         cudaFuncAttributeMaxDynamicSharedMemorySize, SMEM_BYTES);

    init_kernel<<<1, 1>>>();

    const int n16_x = (M_DIM * K_DIM) / 16;
    const int n16_w = (N_DIM * K_DIM) / 16;
    quant_kernel<<<n16_x / 256, 256>>>(x, ia, 0, n16_x);
    quant_kernel<<<n16_w / 256, 256>>>(w, wa, 1, n16_w);

    const int ntiles = (M_DIM / BM) * (N_DIM / BN);   // 2048
    gemm_kernel<<<ntiles, 128, SMEM_BYTES>>>(bias, ia, wa, out);

    finalize_kernel<<<1, 1>>>(ia, wa, out + (size_t)M_DIM * N_DIM);
}

// round 14
// speedup vs baseline: 1.1082x; 1.0031x over previous
#include <cuda_runtime.h>
#include <cuda_bf16.h>
#include <cuda_fp8.h>
#include <cstdint>

// ============================================================================
// out[8192,4096] = fp8_q(x) @ fp8_q(w)^T + bias ; amax EMA scalars at tail.
// sm_103 base ISA: bf16 mma.sync.
// R12: 8-phase K stagger keyed on linear%8 (148 ≡ 4 mod 8 -> co-resident CTAs
//      get different phases) + fused single-launch quantization.
// ============================================================================

#define FP8_MAX   448.0f
#define AMAX_EPS  1e-8f
#define MOMENTUM  0.95f

static constexpr int M_DIM = 8192;
static constexpr int N_DIM = 4096;
static constexpr int K_DIM = 4096;

static constexpr int BM = 128;
static constexpr int BN = 128;
static constexpr int BK = 64;                    // bf16 elems -> 128B rows
static constexpr int STAGES = 3;
static constexpr int KITERS = K_DIM / BK;        // 64

static constexpr int STAGE_A = BM * BK * 2;      // 16384 B
static constexpr int STAGE_B = BN * BK * 2;      // 16384 B
static constexpr int SMEM_BYTES = STAGES * (STAGE_A + STAGE_B);  // 98304

// Scratch: scaled-quantized values stored as bf16 (exact superset of e4m3)
__device__ __nv_bfloat16 g_xb[(size_t)M_DIM * K_DIM];   // 64 MB
__device__ __nv_bfloat16 g_wb[(size_t)N_DIM * K_DIM];   // 32 MB
__device__ float g_amax[2];

// ============================================================================
// helpers
// ============================================================================
__device__ __forceinline__ uint32_t smem_u32(const void* p) {
    uint32_t a;
    asm("{ .reg .u64 t; cvta.to.shared.u64 t, %1; cvt.u32.u64 %0, t; }"
        : "=r"(a) : "l"(p));
    return a;
}

__device__ __forceinline__ void cp16(uint32_t dst, const void* src) {
    asm volatile("cp.async.cg.shared.global [%0], [%1], 16;"
                 :: "r"(dst), "l"(src) : "memory");
}

__device__ __forceinline__ void ldmatrix_x4(uint32_t* r, uint32_t addr) {
    asm volatile("ldmatrix.sync.aligned.m8n8.x4.shared.b16 {%0,%1,%2,%3}, [%4];"
                 : "=r"(r[0]), "=r"(r[1]), "=r"(r[2]), "=r"(r[3]) : "r"(addr));
}

__device__ __forceinline__ void mma_bf16(float* c, const uint32_t* a, const uint32_t* b) {
    asm volatile(
        "mma.sync.aligned.m16n8k16.row.col.f32.bf16.bf16.f32 "
        "{%0,%1,%2,%3}, {%4,%5,%6,%7}, {%8,%9}, {%0,%1,%2,%3};"
        : "+f"(c[0]), "+f"(c[1]), "+f"(c[2]), "+f"(c[3])
        : "r"(a[0]), "r"(a[1]), "r"(a[2]), "r"(a[3]), "r"(b[0]), "r"(b[1]));
}

// ============================================================================
// small kernels
// ============================================================================
__global__ void init_kernel() { g_amax[0] = 0.0f; g_amax[1] = 0.0f; }

// Fused quant for x and w in ONE launch: blocks [0, nxb) do x, rest do w.
// fp32 -> e4m3(RN,satfinite) -> bf16 (exact), scaled; block-reduced abs-max.
__global__ void __launch_bounds__(256) quant_kernel(
    const float* __restrict__ xsrc, const float* __restrict__ wsrc,
    const float* __restrict__ xamax, const float* __restrict__ wamax,
    int nxb)
{
    const int isw = (blockIdx.x >= nxb);
    const float* src = isw ? wsrc : xsrc;
    __nv_bfloat16* dst = isw ? g_wb : g_xb;
    float* gm = &g_amax[isw];
    const int i = (isw ? (blockIdx.x - nxb) : blockIdx.x) * blockDim.x + threadIdx.x;
    const float scale = FP8_MAX / fmaxf(*(isw ? wamax : xamax), AMAX_EPS);

    float m = 0.0f;
    {
        const float4* s4 = reinterpret_cast<const float4*>(src) + (size_t)i * 4;
        uint32_t outw[8];
        #pragma unroll
        for (int j = 0; j < 4; j++) {
            float4 v = s4[j];
            m = fmaxf(m, fmaxf(fmaxf(fabsf(v.x), fabsf(v.y)),
                               fmaxf(fabsf(v.z), fabsf(v.w))));
            float f[4];
            f[0] = v.x * scale; f[1] = v.y * scale;
            f[2] = v.z * scale; f[3] = v.w * scale;
            unsigned short us[4];
            #pragma unroll
            for (int e = 0; e < 4; e++) {
                __nv_fp8_e4m3 q;
                q.__x = __nv_cvt_float_to_fp8(f[e], __NV_SATFINITE, __NV_E4M3);
                us[e] = __bfloat16_as_ushort(__float2bfloat16(float(q)));
            }
            outw[j * 2 + 0] = (uint32_t)us[0] | ((uint32_t)us[1] << 16);
            outw[j * 2 + 1] = (uint32_t)us[2] | ((uint32_t)us[3] << 16);
        }
        uint4* d4 = reinterpret_cast<uint4*>(dst) + (size_t)i * 2;
        d4[0] = make_uint4(outw[0], outw[1], outw[2], outw[3]);
        d4[1] = make_uint4(outw[4], outw[5], outw[6], outw[7]);
    }

    #pragma unroll
    for (int off = 16; off; off >>= 1)
        m = fmaxf(m, __shfl_xor_sync(0xFFFFFFFFu, m, off));
    __shared__ float wmax[8];
    const int wid = threadIdx.x >> 5, lid = threadIdx.x & 31;
    if (lid == 0) wmax[wid] = m;
    __syncthreads();
    if (wid == 0) {
        float mm = (lid < 8) ? wmax[lid] : 0.0f;
        #pragma unroll
        for (int off = 4; off; off >>= 1)
            mm = fmaxf(mm, __shfl_xor_sync(0xFFFFFFFFu, mm, off));
        if (lid == 0)
            atomicMax(reinterpret_cast<int*>(gm), __float_as_int(mm));
    }
}

__global__ void finalize_kernel(const float* __restrict__ ia,
                                const float* __restrict__ wa,
                                float* __restrict__ out_tail)
{
    out_tail[0] = fmaxf(fmaxf(*ia * MOMENTUM, g_amax[0]), AMAX_EPS);
    out_tail[1] = fmaxf(fmaxf(*wa * MOMENTUM, g_amax[1]), AMAX_EPS);
}

// ============================================================================
// GEMM: CTA 128x128x64, 4 warps (2x2), warp tile 64x64, mma.sync bf16
// ============================================================================
__global__ void __launch_bounds__(128, 2)
gemm_kernel(const float* __restrict__ bias,
            const float* __restrict__ ia, const float* __restrict__ wa,
            float* __restrict__ out)
{
    extern __shared__ char smem[];
    const uint32_t sbase = smem_u32(smem);

    // L2-friendly rasterization: group 16 m-tiles
    constexpr int NT = N_DIM / BN;   // 32
    constexpr int G = 16;
    const int linear = blockIdx.x;
    const int group = linear / (G * NT);
    const int rem   = linear % (G * NT);
    const int mtile = group * G + (rem % G);
    const int ntile = rem / G;

    // 8-phase K stagger. 148 ≡ 4 (mod 8) -> co-resident CTAs (bid, bid+148)
    // land 4 phase-groups (=32 k-iters) apart; also spreads L2 bursts chip-wide.
    const int phase = (linear & 7) * (KITERS / 8);

    const int tid = threadIdx.x;
    const int wid = tid >> 5, lane = tid & 31;
    const int warp_m = wid >> 1;          // 0..1 (64 rows each)
    const int warp_n = wid & 1;           // 0..1 (64 cols each)

    __shared__ float bs[BN];
    if (tid < BN) bs[tid] = bias[ntile * BN + tid];

    const __nv_bfloat16* Ag = g_xb + (size_t)mtile * BM * K_DIM;
    const __nv_bfloat16* Bg = g_wb + (size_t)ntile * BN * K_DIM;

    // 1024 16B chunks per tile, 8 per thread (128 threads)
    auto issue_stage = [&](int kiter, int stage) {
        const int kk = (kiter + phase < KITERS) ? (kiter + phase)
                                                : (kiter + phase - KITERS);
        const int k0 = kk * BK;
        const uint32_t sA = sbase + stage * STAGE_A;
        const uint32_t sB = sbase + STAGES * STAGE_A + stage * STAGE_B;
        #pragma unroll
        for (int j = 0; j < 8; j++) {
            int idx = tid + j * 128;
            int row = idx >> 3, c16 = idx & 7;
            uint32_t swcol = (c16 * 16) ^ ((row & 7) << 4);
            cp16(sA + row * 128 + swcol, Ag + (size_t)row * K_DIM + k0 + c16 * 8);
        }
        #pragma unroll
        for (int j = 0; j < 8; j++) {
            int idx = tid + j * 128;
            int row = idx >> 3, c16 = idx & 7;
            uint32_t swcol = (c16 * 16) ^ ((row & 7) << 4);
            cp16(sB + row * 128 + swcol, Bg + (size_t)row * K_DIM + k0 + c16 * 8);
        }
        asm volatile("cp.async.commit_group;" ::: "memory");
    };

    float acc[4][8][4];
    #pragma unroll
    for (int i = 0; i < 4; i++)
        #pragma unroll
        for (int j = 0; j < 8; j++)
            #pragma unroll
            for (int e = 0; e < 4; e++) acc[i][j][e] = 0.0f;

    // prologue: 2 stages in flight
    issue_stage(0, 0);
    issue_stage(1, 1);

    // ldmatrix lane->address mapping
    // A x4: r0=(m0-7,klo) r1=(m8-15,klo) r2=(m0-7,khi) r3=(m8-15,khi)
    const int a_row_l = warp_m * 64 + (lane & 15);
    const uint32_t a_khalf = (lane >> 4) << 4;      // 0 or 16 bytes
    // B x4: r0,r1 = n0-7 pair ; r2,r3 = n8-15 pair
    const int b_row_l = warp_n * 64 + (lane & 7) + ((lane >> 4) << 3);
    const uint32_t b_khalf = ((lane >> 3) & 1) << 4;

    // double-buffered fragments: A 64 rows (4 x4), B 64 cols (4 x4)
    uint32_t afrag[2][4][4], bfrag[2][4][4];

    auto load_frags = [&](int buf, uint32_t sA, uint32_t sB, int ks) {
        #pragma unroll
        for (int mi = 0; mi < 4; mi++) {
            int row = a_row_l + mi * 16;
            uint32_t col = (uint32_t)ks * 32 + a_khalf;
            ldmatrix_x4(afrag[buf][mi], sA + row * 128 + (col ^ ((row & 7) << 4)));
        }
        #pragma unroll
        for (int nh = 0; nh < 4; nh++) {
            int row = b_row_l + nh * 16;
            uint32_t col = (uint32_t)ks * 32 + b_khalf;
            ldmatrix_x4(bfrag[buf][nh], sB + row * 128 + (col ^ ((row & 7) << 4)));
        }
    };

    for (int k = 0; k < KITERS; k++) {
        asm volatile("cp.async.wait_group 1;" ::: "memory");
        __syncthreads();
        // Stage (k+2)%3 was last READ at iter k-1; the sync above guarantees
        // every warp finished those reads -> safe to overwrite.
        if (k + 2 < KITERS) issue_stage(k + 2, (k + 2) % STAGES);
        else asm volatile("cp.async.commit_group;" ::: "memory");

        const int stage = k % STAGES;
        const uint32_t sA = sbase + stage * STAGE_A;
        const uint32_t sB = sbase + STAGES * STAGE_A + stage * STAGE_B;

        load_frags(0, sA, sB, 0);
        #pragma unroll
        for (int ks = 0; ks < BK / 16; ks++) {
            const int cur = ks & 1;
            if (ks + 1 < BK / 16) load_frags(cur ^ 1, sA, sB, ks + 1);
            #pragma unroll
            for (int mi = 0; mi < 4; mi++)
                #pragma unroll
                for (int ni = 0; ni < 8; ni++)
                    mma_bf16(acc[mi][ni], afrag[cur][mi],
                             bfrag[cur][ni >> 1] + (ni & 1) * 2);
        }
    }

    // epilogue: descale + bias
    const float inv = (fmaxf(*ia, AMAX_EPS) * (1.0f / FP8_MAX)) *
                      (fmaxf(*wa, AMAX_EPS) * (1.0f / FP8_MAX));
    const int g = lane >> 2, t = lane & 3;
    #pragma unroll
    for (int mi = 0; mi < 4; mi++) {
        #pragma unroll
        for (int ni = 0; ni < 8; ni++) {
            const int col_l = warp_n * 64 + ni * 8 + t * 2;
            const int col = ntile * BN + col_l;
            const float b0 = bs[col_l], b1 = bs[col_l + 1];
            const int r0 = mtile * BM + warp_m * 64 + mi * 16 + g;
            float2 v0, v1;
            v0.x = acc[mi][ni][0] * inv + b0;
            v0.y = acc[mi][ni][1] * inv + b1;
            v1.x = acc[mi][ni][2] * inv + b0;
            v1.y = acc[mi][ni][3] * inv + b1;
            *reinterpret_cast<float2*>(out + (size_t)r0 * N_DIM + col) = v0;
            *reinterpret_cast<float2*>(out + (size_t)(r0 + 8) * N_DIM + col) = v1;
        }
    }
}

// ============================================================================
// launch
// ============================================================================
extern "C" void kernel_launch(void* const* d_in, const int* in_sizes, int n_in,
                              void* d_out, int out_size)
{
    const float* x    = (const float*)d_in[0];
    const float* w    = (const float*)d_in[1];
    const float* bias = (const float*)d_in[2];
    const float* ia   = (const float*)d_in[3];
    const float* wa   = (const float*)d_in[4];
    float* out = (float*)d_out;

    cudaFuncSetAttribute(gemm_kernel,
                         cudaFuncAttributeMaxDynamicSharedMemorySize, SMEM_BYTES);

    init_kernel<<<1, 1>>>();

    const int n16_x = (M_DIM * K_DIM) / 16;   // 2097152
    const int n16_w = (N_DIM * K_DIM) / 16;   // 1048576
    const int nxb = n16_x / 256;              // 8192 blocks for x
    const int nwb = n16_w / 256;              // 4096 blocks for w
    quant_kernel<<<nxb + nwb, 256>>>(x, w, ia, wa, nxb);

    const int ntiles = (M_DIM / BM) * (N_DIM / BN);   // 2048
    gemm_kernel<<<ntiles, 128, SMEM_BYTES>>>(bias, ia, wa, out);

    finalize_kernel<<<1, 1>>>(ia, wa, out + (size_t)M_DIM * N_DIM);
}

// round 16
// speedup vs baseline: 1.1093x; 1.0010x over previous
#include <cuda_runtime.h>
#include <cuda_bf16.h>
#include <cuda_fp8.h>
#include <cstdint>

// ============================================================================
// out[8192,4096] = fp8_q(x) @ fp8_q(w)^T + bias ; amax EMA scalars at tail.
// sm_103 base ISA: bf16 mma.sync.
// R15: 2 launches only (quant -> gemm). GEMM block 0 emits the amax EMA tail
//      and resets g_amax for the next graph replay (init/finalize fused away).
// ============================================================================

#define FP8_MAX   448.0f
#define AMAX_EPS  1e-8f
#define MOMENTUM  0.95f

static constexpr int M_DIM = 8192;
static constexpr int N_DIM = 4096;
static constexpr int K_DIM = 4096;

static constexpr int BM = 128;
static constexpr int BN = 128;
static constexpr int BK = 64;                    // bf16 elems -> 128B rows
static constexpr int STAGES = 3;
static constexpr int KITERS = K_DIM / BK;        // 64

static constexpr int STAGE_A = BM * BK * 2;      // 16384 B
static constexpr int STAGE_B = BN * BK * 2;      // 16384 B
static constexpr int SMEM_BYTES = STAGES * (STAGE_A + STAGE_B);  // 98304

// Scratch: scaled-quantized values stored as bf16 (exact superset of e4m3)
// g_amax is zero-initialized at module load and reset to 0 by the GEMM kernel
// after each consumption -> every kernel_launch begins with a clean buffer.
__device__ __nv_bfloat16 g_xb[(size_t)M_DIM * K_DIM];   // 64 MB
__device__ __nv_bfloat16 g_wb[(size_t)N_DIM * K_DIM];   // 32 MB
__device__ float g_amax[2];

// ============================================================================
// helpers
// ============================================================================
__device__ __forceinline__ uint32_t smem_u32(const void* p) {
    uint32_t a;
    asm("{ .reg .u64 t; cvta.to.shared.u64 t, %1; cvt.u32.u64 %0, t; }"
        : "=r"(a) : "l"(p));
    return a;
}

__device__ __forceinline__ void cp16(uint32_t dst, const void* src) {
    asm volatile("cp.async.cg.shared.global [%0], [%1], 16;"
                 :: "r"(dst), "l"(src) : "memory");
}

__device__ __forceinline__ void ldmatrix_x4(uint32_t* r, uint32_t addr) {
    asm volatile("ldmatrix.sync.aligned.m8n8.x4.shared.b16 {%0,%1,%2,%3}, [%4];"
                 : "=r"(r[0]), "=r"(r[1]), "=r"(r[2]), "=r"(r[3]) : "r"(addr));
}

__device__ __forceinline__ void mma_bf16(float* c, const uint32_t* a, const uint32_t* b) {
    asm volatile(
        "mma.sync.aligned.m16n8k16.row.col.f32.bf16.bf16.f32 "
        "{%0,%1,%2,%3}, {%4,%5,%6,%7}, {%8,%9}, {%0,%1,%2,%3};"
        : "+f"(c[0]), "+f"(c[1]), "+f"(c[2]), "+f"(c[3])
        : "r"(a[0]), "r"(a[1]), "r"(a[2]), "r"(a[3]), "r"(b[0]), "r"(b[1]));
}

// ============================================================================
// quant: fused x+w in ONE launch. blocks [0, nxb) do x, rest do w.
// fp32 -> e4m3(RN,satfinite) -> bf16 (exact), scaled; block-reduced abs-max.
// ============================================================================
__global__ void __launch_bounds__(256) quant_kernel(
    const float* __restrict__ xsrc, const float* __restrict__ wsrc,
    const float* __restrict__ xamax, const float* __restrict__ wamax,
    int nxb)
{
    const int isw = (blockIdx.x >= nxb);
    const float* src = isw ? wsrc : xsrc;
    __nv_bfloat16* dst = isw ? g_wb : g_xb;
    float* gm = &g_amax[isw];
    const int i = (isw ? (blockIdx.x - nxb) : blockIdx.x) * blockDim.x + threadIdx.x;
    const float scale = FP8_MAX / fmaxf(*(isw ? wamax : xamax), AMAX_EPS);

    float m = 0.0f;
    {
        const float4* s4 = reinterpret_cast<const float4*>(src) + (size_t)i * 4;
        uint32_t outw[8];
        #pragma unroll
        for (int j = 0; j < 4; j++) {
            float4 v = s4[j];
            m = fmaxf(m, fmaxf(fmaxf(fabsf(v.x), fabsf(v.y)),
                               fmaxf(fabsf(v.z), fabsf(v.w))));
            float f[4];
            f[0] = v.x * scale; f[1] = v.y * scale;
            f[2] = v.z * scale; f[3] = v.w * scale;
            unsigned short us[4];
            #pragma unroll
            for (int e = 0; e < 4; e++) {
                __nv_fp8_e4m3 q;
                q.__x = __nv_cvt_float_to_fp8(f[e], __NV_SATFINITE, __NV_E4M3);
                us[e] = __bfloat16_as_ushort(__float2bfloat16(float(q)));
            }
            outw[j * 2 + 0] = (uint32_t)us[0] | ((uint32_t)us[1] << 16);
            outw[j * 2 + 1] = (uint32_t)us[2] | ((uint32_t)us[3] << 16);
        }
        uint4* d4 = reinterpret_cast<uint4*>(dst) + (size_t)i * 2;
        d4[0] = make_uint4(outw[0], outw[1], outw[2], outw[3]);
        d4[1] = make_uint4(outw[4], outw[5], outw[6], outw[7]);
    }

    #pragma unroll
    for (int off = 16; off; off >>= 1)
        m = fmaxf(m, __shfl_xor_sync(0xFFFFFFFFu, m, off));
    __shared__ float wmax[8];
    const int wid = threadIdx.x >> 5, lid = threadIdx.x & 31;
    if (lid == 0) wmax[wid] = m;
    __syncthreads();
    if (wid == 0) {
        float mm = (lid < 8) ? wmax[lid] : 0.0f;
        #pragma unroll
        for (int off = 4; off; off >>= 1)
            mm = fmaxf(mm, __shfl_xor_sync(0xFFFFFFFFu, mm, off));
        if (lid == 0)
            atomicMax(reinterpret_cast<int*>(gm), __float_as_int(mm));
    }
}

// ============================================================================
// GEMM: CTA 128x128x64, 4 warps (2x2), warp tile 64x64, mma.sync bf16.
// Block 0 also emits the amax EMA tail and resets g_amax (stream-ordered
// after quant; reset makes the next graph replay deterministic).
// ============================================================================
__global__ void __launch_bounds__(128, 2)
gemm_kernel(const float* __restrict__ bias,
            const float* __restrict__ ia, const float* __restrict__ wa,
            float* __restrict__ out)
{
    extern __shared__ char smem[];
    const uint32_t sbase = smem_u32(smem);

    // L2-friendly rasterization: group 16 m-tiles
    constexpr int NT = N_DIM / BN;   // 32
    constexpr int G = 16;
    const int linear = blockIdx.x;
    const int group = linear / (G * NT);
    const int rem   = linear % (G * NT);
    const int mtile = group * G + (rem % G);
    const int ntile = rem / G;

    // fused amax EMA tail + reset (one thread, one block)
    if (linear == 0 && threadIdx.x == 0) {
        float a0 = g_amax[0], a1 = g_amax[1];
        float* tail = out + (size_t)M_DIM * N_DIM;
        tail[0] = fmaxf(fmaxf(*ia * MOMENTUM, a0), AMAX_EPS);
        tail[1] = fmaxf(fmaxf(*wa * MOMENTUM, a1), AMAX_EPS);
        g_amax[0] = 0.0f;
        g_amax[1] = 0.0f;
    }

    // K-phase stagger (chip-wide L2/traffic spreading; R11/R12-validated)
    const int phase = (linear & 7) * (KITERS / 8);

    const int tid = threadIdx.x;
    const int wid = tid >> 5, lane = tid & 31;
    const int warp_m = wid >> 1;          // 0..1 (64 rows each)
    const int warp_n = wid & 1;           // 0..1 (64 cols each)

    __shared__ float bs[BN];
    if (tid < BN) bs[tid] = bias[ntile * BN + tid];

    const __nv_bfloat16* Ag = g_xb + (size_t)mtile * BM * K_DIM;
    const __nv_bfloat16* Bg = g_wb + (size_t)ntile * BN * K_DIM;

    // 1024 16B chunks per tile, 8 per thread (128 threads)
    auto issue_stage = [&](int kiter, int stage) {
        const int kk = (kiter + phase < KITERS) ? (kiter + phase)
                                                : (kiter + phase - KITERS);
        const int k0 = kk * BK;
        const uint32_t sA = sbase + stage * STAGE_A;
        const uint32_t sB = sbase + STAGES * STAGE_A + stage * STAGE_B;
        #pragma unroll
        for (int j = 0; j < 8; j++) {
            int idx = tid + j * 128;
            int row = idx >> 3, c16 = idx & 7;
            uint32_t swcol = (c16 * 16) ^ ((row & 7) << 4);
            cp16(sA + row * 128 + swcol, Ag + (size_t)row * K_DIM + k0 + c16 * 8);
        }
        #pragma unroll
        for (int j = 0; j < 8; j++) {
            int idx = tid + j * 128;
            int row = idx >> 3, c16 = idx & 7;
            uint32_t swcol = (c16 * 16) ^ ((row & 7) << 4);
            cp16(sB + row * 128 + swcol, Bg + (size_t)row * K_DIM + k0 + c16 * 8);
        }
        asm volatile("cp.async.commit_group;" ::: "memory");
    };

    float acc[4][8][4];
    #pragma unroll
    for (int i = 0; i < 4; i++)
        #pragma unroll
        for (int j = 0; j < 8; j++)
            #pragma unroll
            for (int e = 0; e < 4; e++) acc[i][j][e] = 0.0f;

    // prologue: 2 stages in flight
    issue_stage(0, 0);
    issue_stage(1, 1);

    // ldmatrix lane->address mapping
    // A x4: r0=(m0-7,klo) r1=(m8-15,klo) r2=(m0-7,khi) r3=(m8-15,khi)
    const int a_row_l = warp_m * 64 + (lane & 15);
    const uint32_t a_khalf = (lane >> 4) << 4;      // 0 or 16 bytes
    // B x4: r0,r1 = n0-7 pair ; r2,r3 = n8-15 pair
    const int b_row_l = warp_n * 64 + (lane & 7) + ((lane >> 4) << 3);
    const uint32_t b_khalf = ((lane >> 3) & 1) << 4;

    // double-buffered fragments: A 64 rows (4 x4), B 64 cols (4 x4)
    uint32_t afrag[2][4][4], bfrag[2][4][4];

    auto load_frags = [&](int buf, uint32_t sA, uint32_t sB, int ks) {
        #pragma unroll
        for (int mi = 0; mi < 4; mi++) {
            int row = a_row_l + mi * 16;
            uint32_t col = (uint32_t)ks * 32 + a_khalf;
            ldmatrix_x4(afrag[buf][mi], sA + row * 128 + (col ^ ((row & 7) << 4)));
        }
        #pragma unroll
        for (int nh = 0; nh < 4; nh++) {
            int row = b_row_l + nh * 16;
            uint32_t col = (uint32_t)ks * 32 + b_khalf;
            ldmatrix_x4(bfrag[buf][nh], sB + row * 128 + (col ^ ((row & 7) << 4)));
        }
    };

    for (int k = 0; k < KITERS; k++) {
        asm volatile("cp.async.wait_group 1;" ::: "memory");
        __syncthreads();
        // Stage (k+2)%3 was last READ at iter k-1; the sync above guarantees
        // every warp finished those reads -> safe to overwrite.
        if (k + 2 < KITERS) issue_stage(k + 2, (k + 2) % STAGES);
        else asm volatile("cp.async.commit_group;" ::: "memory");

        const int stage = k % STAGES;
        const uint32_t sA = sbase + stage * STAGE_A;
        const uint32_t sB = sbase + STAGES * STAGE_A + stage * STAGE_B;

        load_frags(0, sA, sB, 0);
        #pragma unroll
        for (int ks = 0; ks < BK / 16; ks++) {
            const int cur = ks & 1;
            if (ks + 1 < BK / 16) load_frags(cur ^ 1, sA, sB, ks + 1);
            #pragma unroll
            for (int mi = 0; mi < 4; mi++)
                #pragma unroll
                for (int ni = 0; ni < 8; ni++)
                    mma_bf16(acc[mi][ni], afrag[cur][mi],
                             bfrag[cur][ni >> 1] + (ni & 1) * 2);
        }
    }

    // epilogue: descale + bias
    const float inv = (fmaxf(*ia, AMAX_EPS) * (1.0f / FP8_MAX)) *
                      (fmaxf(*wa, AMAX_EPS) * (1.0f / FP8_MAX));
    const int g = lane >> 2, t = lane & 3;
    #pragma unroll
    for (int mi = 0; mi < 4; mi++) {
        #pragma unroll
        for (int ni = 0; ni < 8; ni++) {
            const int col_l = warp_n * 64 + ni * 8 + t * 2;
            const int col = ntile * BN + col_l;
            const float b0 = bs[col_l], b1 = bs[col_l + 1];
            const int r0 = mtile * BM + warp_m * 64 + mi * 16 + g;
            float2 v0, v1;
            v0.x = acc[mi][ni][0] * inv + b0;
            v0.y = acc[mi][ni][1] * inv + b1;
            v1.x = acc[mi][ni][2] * inv + b0;
            v1.y = acc[mi][ni][3] * inv + b1;
            *reinterpret_cast<float2*>(out + (size_t)r0 * N_DIM + col) = v0;
            *reinterpret_cast<float2*>(out + (size_t)(r0 + 8) * N_DIM + col) = v1;
        }
    }
}

// ============================================================================
// launch: two kernels total
// ============================================================================
extern "C" void kernel_launch(void* const* d_in, const int* in_sizes, int n_in,
                              void* d_out, int out_size)
{
    const float* x    = (const float*)d_in[0];
    const float* w    = (const float*)d_in[1];
    const float* bias = (const float*)d_in[2];
    const float* ia   = (const float*)d_in[3];
    const float* wa   = (const float*)d_in[4];
    float* out = (float*)d_out;

    cudaFuncSetAttribute(gemm_kernel,
                         cudaFuncAttributeMaxDynamicSharedMemorySize, SMEM_BYTES);

    const int n16_x = (M_DIM * K_DIM) / 16;   // 2097152
    const int n16_w = (N_DIM * K_DIM) / 16;   // 1048576
    const int nxb = n16_x / 256;              // 8192 blocks for x
    const int nwb = n16_w / 256;              // 4096 blocks for w
    quant_kernel<<<nxb + nwb, 256>>>(x, w, ia, wa, nxb);

    const int ntiles = (M_DIM / BM) * (N_DIM / BN);   // 2048
    gemm_kernel<<<ntiles, 128, SMEM_BYTES>>>(bias, ia, wa, out);
}